// round 15
// baseline (speedup 1.0000x reference)
#include <cuda_runtime.h>
#include <cuda_fp16.h>
#include <cstdint>
#include <cstddef>

#define T_TOK 2048
#define H_DIM 2048
#define N_EXP 32
#define I_DIM 768
#define TOPK  8
#define PITCH 80        // smem row pitch bytes (32 halves + 16B skew)

// -------- static device scratch --------------------------------------------
__device__ int   g_cnt[N_EXP];
__device__ int   g_list[N_EXP * T_TOK];
__device__ float g_rw[T_TOK * TOPK];
__device__ __align__(16) __half g_xh[(size_t)T_TOK * H_DIM];          // 8 MB
__device__ __align__(16) __half g_wdh[(size_t)N_EXP * H_DIM * I_DIM]; // 96 MB
__device__ __align__(16) __half g_h[(size_t)T_TOK * TOPK * I_DIM];    // 25 MB

// -------- helpers -----------------------------------------------------------
__device__ __forceinline__ uint32_t sptr(const void* p) {
    return (uint32_t)__cvta_generic_to_shared(p);
}
__device__ __forceinline__ uint32_t pk2(float a, float b) {
    __half2 h = __floats2half2_rn(a, b);
    return *(uint32_t*)&h;
}
__device__ __forceinline__ void sts128(uint32_t a, uint32_t x0, uint32_t x1,
                                       uint32_t x2, uint32_t x3) {
    asm volatile("st.shared.v4.b32 [%0], {%1,%2,%3,%4};"
                 :: "r"(a), "r"(x0), "r"(x1), "r"(x2), "r"(x3));
}
__device__ __forceinline__ void cp16(uint32_t dst, const void* src, int valid) {
    asm volatile("cp.async.cg.shared.global [%0], [%1], 16, %2;"
                 :: "r"(dst), "l"(src), "r"(valid ? 16 : 0));
}
#define CP_COMMIT() asm volatile("cp.async.commit_group;")
#define CP_WAIT0()  asm volatile("cp.async.wait_group 0;")

__device__ __forceinline__ void ldsm4(uint32_t* r, uint32_t a) {
    asm volatile("ldmatrix.sync.aligned.m8n8.x4.shared.b16 {%0,%1,%2,%3}, [%4];"
                 : "=r"(r[0]), "=r"(r[1]), "=r"(r[2]), "=r"(r[3]) : "r"(a));
}
__device__ __forceinline__ void mma16(float* d, const uint32_t* a,
                                      uint32_t b0, uint32_t b1) {
    asm volatile(
        "mma.sync.aligned.m16n8k16.row.col.f32.f16.f16.f32 "
        "{%0,%1,%2,%3},{%4,%5,%6,%7},{%8,%9},{%0,%1,%2,%3};"
        : "+f"(d[0]), "+f"(d[1]), "+f"(d[2]), "+f"(d[3])
        : "r"(a[0]), "r"(a[1]), "r"(a[2]), "r"(a[3]), "r"(b0), "r"(b1));
}

// -------- init: zero counters + output ----------------------------------------
__global__ __launch_bounds__(256) void init_kernel(float* __restrict__ out, int n)
{
    int i = blockIdx.x * 256 + threadIdx.x;
    if (i < N_EXP) g_cnt[i] = 0;
    for (int j = i; j < n; j += gridDim.x * 256) out[j] = 0.f;
}

// -------- fp32 -> fp16 streaming convert (8 elements / thread) ---------------
__global__ __launch_bounds__(256) void conv_kernel(
    const float* __restrict__ src, __half* __restrict__ dst)
{
    size_t i = (size_t)blockIdx.x * 256 + threadIdx.x;
    const float4* s = (const float4*)src + i * 2;
    float4 v0 = s[0], v1 = s[1];
    uint4 o;
    o.x = pk2(v0.x, v0.y); o.y = pk2(v0.z, v0.w);
    o.z = pk2(v1.x, v1.y); o.w = pk2(v1.z, v1.w);
    *(uint4*)&dst[i * 8] = o;
}

// -------- router (also emits x in fp16 to g_xh) --------------------------------
__global__ __launch_bounds__(256) void router_kernel(
    const float* __restrict__ x, const float* __restrict__ gw)
{
    __shared__ float xs[H_DIM];
    __shared__ float logits[N_EXP];

    const int t = blockIdx.x;
    const float* xr = x + (size_t)t * H_DIM;
    for (int i = threadIdx.x; i < H_DIM; i += 256) xs[i] = xr[i];
    __syncthreads();

    {
        const int b = threadIdx.x * 8;
        uint4 o;
        o.x = pk2(xs[b + 0], xs[b + 1]);
        o.y = pk2(xs[b + 2], xs[b + 3]);
        o.z = pk2(xs[b + 4], xs[b + 5]);
        o.w = pk2(xs[b + 6], xs[b + 7]);
        *(uint4*)&g_xh[(size_t)t * H_DIM + b] = o;
    }

    const int warp = threadIdx.x >> 5;
    const int lane = threadIdx.x & 31;

    float acc[4] = {0.f, 0.f, 0.f, 0.f};
    for (int k = lane; k < H_DIM; k += 32) {
        float xv = xs[k];
        #pragma unroll
        for (int q = 0; q < 4; q++)
            acc[q] = fmaf(xv, gw[(size_t)(warp * 4 + q) * H_DIM + k], acc[q]);
    }
    #pragma unroll
    for (int q = 0; q < 4; q++) {
        float v = acc[q];
        #pragma unroll
        for (int off = 16; off; off >>= 1)
            v += __shfl_down_sync(0xffffffffu, v, off);
        if (lane == 0) logits[warp * 4 + q] = v;
    }
    __syncthreads();

    if (threadIdx.x == 0) {
        float lg[N_EXP];
        #pragma unroll
        for (int i = 0; i < N_EXP; i++) lg[i] = logits[i];
        int   sel[TOPK];
        float sv[TOPK];
        #pragma unroll
        for (int s = 0; s < TOPK; s++) {
            int best = 0; float bv = -3.4e38f;
            #pragma unroll
            for (int i = 0; i < N_EXP; i++)
                if (lg[i] > bv) { bv = lg[i]; best = i; }
            sel[s] = best; sv[s] = bv; lg[best] = -3.4e38f;
        }
        float mx = sv[0];
        float ex[TOPK], sum = 0.f;
        #pragma unroll
        for (int s = 0; s < TOPK; s++) { ex[s] = __expf(sv[s] - mx); sum += ex[s]; }
        float inv = 1.f / sum;
        #pragma unroll
        for (int s = 0; s < TOPK; s++) {
            int e = sel[s];
            int pos = atomicAdd(&g_cnt[e], 1);
            g_list[e * T_TOK + pos] = t * TOPK + s;
            g_rw[t * TOPK + s] = ex[s] * inv;
        }
    }
}

// ============================================================================
// phase A: h = silu(x@Wg^T)*(x@Wu^T)*rw     fp16 MMA m16n8k16, fp32 accum
// (identical to round-14 best: merged-B ldsm4, manual kt unroll x2)
// ============================================================================
__global__ __launch_bounds__(256, 2) void phaseA_kernel(
    const float* __restrict__ wg, const float* __restrict__ wu)
{
    const int e    = blockIdx.z;
    const int cnt  = g_cnt[e];
    const int row0 = blockIdx.x * 128;
    if (row0 >= cnt) return;
    const int col0 = blockIdx.y * 64;

    extern __shared__ __align__(16) char dsm[];
    __shared__ int toks[128];

    const uint32_t S   = sptr(dsm);
    const uint32_t A0  = S;
    const uint32_t G0  = S + 10240;
    const uint32_t U0  = S + 15360;
    const uint32_t STG = 20480;

    const int tid = threadIdx.x;
    if (tid < 128) {
        int r = row0 + tid;
        toks[tid] = (r < cnt) ? g_list[e * T_TOK + r] : -1;
    }
    __syncthreads();

    const float* wgE = wg + (size_t)e * I_DIM * H_DIM + (size_t)col0 * H_DIM;
    const float* wuE = wu + (size_t)e * I_DIM * H_DIM + (size_t)col0 * H_DIM;

    const int warp = tid >> 5, lane = tid & 31;
    const int gid  = lane >> 2, tcol = lane & 3;
    const int mw0  = (warp & 1) * 64;
    const int nw0  = (warp >> 1) * 16;

    const uint32_t aoff = (uint32_t)(mw0 + (lane & 15)) * PITCH + ((lane >> 4) * 16);
    const uint32_t boff = (uint32_t)(nw0 + ((lane >> 4) << 3) + (lane & 7)) * PITCH
                        + (((lane >> 3) & 1) * 16);

    float accG[4][2][4] = {};
    float accU[4][2][4] = {};
    float4 gq[2], uq[2];

    const int wr = tid >> 2;
    const int wc = tid & 3;

    auto ldgA = [&](int kt, int buf) {
        const int k0 = kt * 32;
        #pragma unroll
        for (int j = 0; j < 2; j++) {
            int idx = j * 256 + tid;
            int r   = idx >> 2;
            int ch  = idx & 3;
            int pkk = toks[r];
            const __half* src = (pkk >= 0)
                ? &g_xh[(size_t)(pkk >> 3) * H_DIM + k0 + ch * 8] : g_xh;
            cp16(A0 + buf * STG + r * PITCH + ch * 16, src, pkk >= 0);
        }
    };
    auto ldgW = [&](int kt) {
        const int k0 = kt * 32;
        const float* sg = &wgE[(size_t)wr * H_DIM + k0 + wc * 8];
        const float* su = &wuE[(size_t)wr * H_DIM + k0 + wc * 8];
        gq[0] = *(const float4*)sg; gq[1] = *(const float4*)(sg + 4);
        uq[0] = *(const float4*)su; uq[1] = *(const float4*)(su + 4);
    };
    auto stsW = [&](int buf) {
        uint32_t a = G0 + buf * STG + wr * PITCH + wc * 16;
        sts128(a, pk2(gq[0].x, gq[0].y), pk2(gq[0].z, gq[0].w),
                  pk2(gq[1].x, gq[1].y), pk2(gq[1].z, gq[1].w));
        uint32_t b = U0 + buf * STG + wr * PITCH + wc * 16;
        sts128(b, pk2(uq[0].x, uq[0].y), pk2(uq[0].z, uq[0].w),
                  pk2(uq[1].x, uq[1].y), pk2(uq[1].z, uq[1].w));
    };
    auto compute = [&](int buf) {
        const uint32_t Ab = A0 + buf * STG + aoff;
        const uint32_t Gb = G0 + buf * STG + boff;
        const uint32_t Ub = U0 + buf * STG + boff;
        #pragma unroll
        for (int kc = 0; kc < 2; kc++) {
            const uint32_t kb = kc * 32;
            uint32_t a[4][4];
            #pragma unroll
            for (int mf = 0; mf < 4; mf++) ldsm4(a[mf], Ab + mf * 16 * PITCH + kb);
            uint32_t bg[4], bu[4];
            ldsm4(bg, Gb + kb);
            ldsm4(bu, Ub + kb);
            #pragma unroll
            for (int mf = 0; mf < 4; mf++) {
                mma16(accG[mf][0], a[mf], bg[0], bg[1]);
                mma16(accG[mf][1], a[mf], bg[2], bg[3]);
                mma16(accU[mf][0], a[mf], bu[0], bu[1]);
                mma16(accU[mf][1], a[mf], bu[2], bu[3]);
            }
        }
    };

    const int KT = H_DIM / 32;   // 64 (even)
    ldgA(0, 0); CP_COMMIT();
    ldgW(0);

    for (int kt = 0; kt < KT; kt += 2) {
        stsW(0);
        CP_WAIT0();
        __syncthreads();
        ldgA(kt + 1, 1); CP_COMMIT();
        ldgW(kt + 1);
        compute(0);
        stsW(1);
        CP_WAIT0();
        __syncthreads();
        if (kt + 2 < KT) {
            ldgA(kt + 2, 0); CP_COMMIT();
            ldgW(kt + 2);
        }
        compute(1);
    }

    #pragma unroll
    for (int mf = 0; mf < 4; mf++) {
        #pragma unroll
        for (int half = 0; half < 2; half++) {
            int rl = mw0 + mf * 16 + gid + half * 8;
            int pkk = toks[rl];
            if (pkk < 0) continue;
            float w = g_rw[pkk];
            #pragma unroll
            for (int nf = 0; nf < 2; nf++) {
                int c = col0 + nw0 + nf * 8 + 2 * tcol;
                float g0 = accG[mf][nf][half * 2 + 0];
                float g1 = accG[mf][nf][half * 2 + 1];
                float u0 = accU[mf][nf][half * 2 + 0];
                float u1 = accU[mf][nf][half * 2 + 1];
                float h0 = (g0 / (1.f + __expf(-g0))) * u0 * w;
                float h1 = (g1 / (1.f + __expf(-g1))) * u1 * w;
                *(uint32_t*)&g_h[(size_t)pkk * I_DIM + c] = pk2(h0, h1);
            }
        }
    }
}

// ============================================================================
// phase B: out[token] += h[pk] @ Wd^T   fp16 MMA, fp32 accum, atomic epilogue
// BM=128, BN=128, BK=32; all-cp.async staging (H + fp16 Wd), unroll x2.
// ============================================================================
__global__ __launch_bounds__(256, 2) void phaseB_kernel(float* __restrict__ out)
{
    const int e    = blockIdx.z;
    const int cnt  = g_cnt[e];
    const int row0 = blockIdx.x * 128;
    if (row0 >= cnt) return;
    const int col0 = blockIdx.y * 128;

    extern __shared__ __align__(16) char dsm[];
    __shared__ int toks[128];

    const uint32_t S   = sptr(dsm);
    const uint32_t H0  = S;
    const uint32_t D0  = S + 10240;
    const uint32_t STG = 20480;

    const int tid = threadIdx.x;
    if (tid < 128) {
        int r = row0 + tid;
        toks[tid] = (r < cnt) ? g_list[e * T_TOK + r] : -1;
    }
    __syncthreads();

    const __half* wdE = g_wdh + (size_t)e * H_DIM * I_DIM + (size_t)col0 * I_DIM;

    const int warp = tid >> 5, lane = tid & 31;
    const int gid  = lane >> 2, tcol = lane & 3;
    const int mw0  = (warp & 1) * 64;
    const int nw0  = (warp >> 1) * 32;

    const uint32_t aoff = (uint32_t)(mw0 + (lane & 15)) * PITCH + ((lane >> 4) * 16);
    const uint32_t boff = (uint32_t)(nw0 + (lane & 15)) * PITCH + ((lane >> 4) * 16);

    float acc[4][4][4] = {};

    // hoisted staging pointers: 2 H rows + 2 D rows per thread
    const int ar0 = tid >> 2;
    const int sch = tid & 3;

    const int pk0 = toks[ar0], pk1 = toks[ar0 + 64];
    const __half* hS0 = (pk0 >= 0) ? &g_h[(size_t)pk0 * I_DIM + sch * 8] : g_h;
    const __half* hS1 = (pk1 >= 0) ? &g_h[(size_t)pk1 * I_DIM + sch * 8] : g_h;
    const __half* dS0 = &wdE[(size_t)ar0 * I_DIM + sch * 8];
    const __half* dS1 = &wdE[(size_t)(ar0 + 64) * I_DIM + sch * 8];
    const uint32_t hD0 = H0 + ar0 * PITCH + sch * 16;
    const uint32_t hD1 = H0 + (ar0 + 64) * PITCH + sch * 16;
    const uint32_t dD0 = D0 + ar0 * PITCH + sch * 16;
    const uint32_t dD1 = D0 + (ar0 + 64) * PITCH + sch * 16;

    auto stage = [&](int kt, int buf) {
        const int k0 = kt * 32;
        const uint32_t bo = buf * STG;
        cp16(hD0 + bo, hS0 + k0, pk0 >= 0);
        cp16(hD1 + bo, hS1 + k0, pk1 >= 0);
        cp16(dD0 + bo, dS0 + k0, 1);
        cp16(dD1 + bo, dS1 + k0, 1);
    };
    auto compute = [&](int buf) {
        const uint32_t Hb = H0 + buf * STG + aoff;
        const uint32_t Db = D0 + buf * STG + boff;
        #pragma unroll
        for (int kc = 0; kc < 2; kc++) {
            const uint32_t kb = kc * 32;
            uint32_t a[4][4];
            #pragma unroll
            for (int mf = 0; mf < 4; mf++) ldsm4(a[mf], Hb + mf * 16 * PITCH + kb);
            uint32_t b[2][4];
            #pragma unroll
            for (int g = 0; g < 2; g++) ldsm4(b[g], Db + g * 16 * PITCH + kb);
            #pragma unroll
            for (int mf = 0; mf < 4; mf++)
                #pragma unroll
                for (int g = 0; g < 2; g++) {
                    mma16(acc[mf][g * 2 + 0], a[mf], b[g][0], b[g][2]);
                    mma16(acc[mf][g * 2 + 1], a[mf], b[g][1], b[g][3]);
                }
        }
    };

    const int KT = I_DIM / 32;   // 24 (even)
    stage(0, 0); CP_COMMIT();

    for (int kt = 0; kt < KT; kt += 2) {
        CP_WAIT0();
        __syncthreads();
        stage(kt + 1, 1); CP_COMMIT();
        compute(0);
        CP_WAIT0();
        __syncthreads();
        if (kt + 2 < KT) { stage(kt + 2, 0); CP_COMMIT(); }
        compute(1);
    }

    // epilogue: atomic accumulate into out
    #pragma unroll
    for (int mf = 0; mf < 4; mf++) {
        #pragma unroll
        for (int half = 0; half < 2; half++) {
            int rl = mw0 + mf * 16 + gid + half * 8;
            int pkk = toks[rl];
            if (pkk < 0) continue;
            float* orow = out + (size_t)(pkk >> 3) * H_DIM;
            #pragma unroll
            for (int nf = 0; nf < 4; nf++) {
                int c = col0 + nw0 + nf * 8 + 2 * tcol;
                atomicAdd(&orow[c],     acc[mf][nf][half * 2 + 0]);
                atomicAdd(&orow[c + 1], acc[mf][nf][half * 2 + 1]);
            }
        }
    }
}

// ---------------------------------------------------------------------------
extern "C" void kernel_launch(void* const* d_in, const int* in_sizes, int n_in,
                              void* d_out, int out_size)
{
    const float* x  = (const float*)d_in[0];
    const float* gw = (const float*)d_in[1];
    const float* wg = (const float*)d_in[2];
    const float* wu = (const float*)d_in[3];
    const float* wd = (const float*)d_in[4];
    float* out = (float*)d_out;

    const int smemAB = 2 * 20480;   // 40960 B

    static cudaStream_t s2 = nullptr;
    static cudaEvent_t evRoot = nullptr, evD = nullptr;
    if (!s2) {
        cudaFuncSetAttribute(phaseA_kernel, cudaFuncAttributeMaxDynamicSharedMemorySize, smemAB);
        cudaFuncSetAttribute(phaseB_kernel, cudaFuncAttributeMaxDynamicSharedMemorySize, smemAB);
        cudaStreamCreateWithFlags(&s2, cudaStreamNonBlocking);
        cudaEventCreateWithFlags(&evRoot, cudaEventDisableTiming);
        cudaEventCreateWithFlags(&evD, cudaEventDisableTiming);
    }

    __half* wdh_p;
    cudaGetSymbolAddress((void**)&wdh_p, g_wdh);

    const int W_ELEM = N_EXP * I_DIM * H_DIM;   // 50331648

    // fork: Wd conversion on s2; hidden under router + phaseA (DRAM-light)
    cudaEventRecord(evRoot, 0);
    cudaStreamWaitEvent(s2, evRoot, 0);
    conv_kernel<<<(W_ELEM / 8) / 256, 256, 0, s2>>>(wd, wdh_p);
    cudaEventRecord(evD, s2);

    // main stream
    init_kernel<<<1024, 256>>>(out, out_size);
    router_kernel<<<T_TOK, 256>>>(x, gw);
    phaseA_kernel<<<dim3(16, I_DIM / 64, N_EXP), 256, smemAB>>>(wg, wu);
    cudaStreamWaitEvent(0, evD, 0);
    phaseB_kernel<<<dim3(16, H_DIM / 128, N_EXP), 256, smemAB>>>(out);
}

// round 16
// speedup vs baseline: 1.0163x; 1.0163x over previous
#include <cuda_runtime.h>
#include <cuda_fp16.h>
#include <cstdint>
#include <cstddef>

#define T_TOK 2048
#define H_DIM 2048
#define N_EXP 32
#define I_DIM 768
#define TOPK  8
#define PITCH 80        // smem row pitch bytes (32 halves + 16B skew)

// -------- static device scratch --------------------------------------------
__device__ int   g_cnt[N_EXP];
__device__ int   g_list[N_EXP * T_TOK];
__device__ float g_rw[T_TOK * TOPK];
__device__ __align__(16) __half g_xh[(size_t)T_TOK * H_DIM];        // 8 MB  x fp16
__device__ __align__(16) __half g_h[(size_t)T_TOK * TOPK * I_DIM];  // 25 MB h fp16

// -------- helpers -----------------------------------------------------------
__device__ __forceinline__ uint32_t sptr(const void* p) {
    return (uint32_t)__cvta_generic_to_shared(p);
}
__device__ __forceinline__ uint32_t pk2(float a, float b) {
    __half2 h = __floats2half2_rn(a, b);
    return *(uint32_t*)&h;
}
__device__ __forceinline__ void sts128(uint32_t a, uint32_t x0, uint32_t x1,
                                       uint32_t x2, uint32_t x3) {
    asm volatile("st.shared.v4.b32 [%0], {%1,%2,%3,%4};"
                 :: "r"(a), "r"(x0), "r"(x1), "r"(x2), "r"(x3));
}
__device__ __forceinline__ void cp16(uint32_t dst, const void* src, int valid) {
    asm volatile("cp.async.cg.shared.global [%0], [%1], 16, %2;"
                 :: "r"(dst), "l"(src), "r"(valid ? 16 : 0));
}
#define CP_COMMIT() asm volatile("cp.async.commit_group;")
#define CP_WAIT0()  asm volatile("cp.async.wait_group 0;")

__device__ __forceinline__ void ldsm4(uint32_t* r, uint32_t a) {
    asm volatile("ldmatrix.sync.aligned.m8n8.x4.shared.b16 {%0,%1,%2,%3}, [%4];"
                 : "=r"(r[0]), "=r"(r[1]), "=r"(r[2]), "=r"(r[3]) : "r"(a));
}
__device__ __forceinline__ void mma16(float* d, const uint32_t* a,
                                      uint32_t b0, uint32_t b1) {
    asm volatile(
        "mma.sync.aligned.m16n8k16.row.col.f32.f16.f16.f32 "
        "{%0,%1,%2,%3},{%4,%5,%6,%7},{%8,%9},{%0,%1,%2,%3};"
        : "+f"(d[0]), "+f"(d[1]), "+f"(d[2]), "+f"(d[3])
        : "r"(a[0]), "r"(a[1]), "r"(a[2]), "r"(a[3]), "r"(b0), "r"(b1));
}

// -------- init: zero expert counters only -------------------------------------
__global__ void init_kernel()
{
    if (threadIdx.x < N_EXP) g_cnt[threadIdx.x] = 0;
}

// -------- router (emits x fp16 to g_xh; zeroes its token's out row) -----------
__global__ __launch_bounds__(256) void router_kernel(
    const float* __restrict__ x, const float* __restrict__ gw,
    float* __restrict__ out)
{
    __shared__ float xs[H_DIM];
    __shared__ float logits[N_EXP];

    const int t = blockIdx.x;
    const float* xr = x + (size_t)t * H_DIM;
    for (int i = threadIdx.x; i < H_DIM; i += 256) xs[i] = xr[i];

    // zero this token's output row (512 float4 over 256 threads)
    {
        float4 z = make_float4(0.f, 0.f, 0.f, 0.f);
        float4* orow = (float4*)(out + (size_t)t * H_DIM);
        orow[threadIdx.x]       = z;
        orow[threadIdx.x + 256] = z;
    }
    __syncthreads();

    // fused: write this token's row as fp16 (8 elements / thread)
    {
        const int b = threadIdx.x * 8;
        uint4 o;
        o.x = pk2(xs[b + 0], xs[b + 1]);
        o.y = pk2(xs[b + 2], xs[b + 3]);
        o.z = pk2(xs[b + 4], xs[b + 5]);
        o.w = pk2(xs[b + 6], xs[b + 7]);
        *(uint4*)&g_xh[(size_t)t * H_DIM + b] = o;
    }

    const int warp = threadIdx.x >> 5;
    const int lane = threadIdx.x & 31;

    float acc[4] = {0.f, 0.f, 0.f, 0.f};
    for (int k = lane; k < H_DIM; k += 32) {
        float xv = xs[k];
        #pragma unroll
        for (int q = 0; q < 4; q++)
            acc[q] = fmaf(xv, gw[(size_t)(warp * 4 + q) * H_DIM + k], acc[q]);
    }
    #pragma unroll
    for (int q = 0; q < 4; q++) {
        float v = acc[q];
        #pragma unroll
        for (int off = 16; off; off >>= 1)
            v += __shfl_down_sync(0xffffffffu, v, off);
        if (lane == 0) logits[warp * 4 + q] = v;
    }
    __syncthreads();

    if (threadIdx.x == 0) {
        float lg[N_EXP];
        #pragma unroll
        for (int i = 0; i < N_EXP; i++) lg[i] = logits[i];
        int   sel[TOPK];
        float sv[TOPK];
        #pragma unroll
        for (int s = 0; s < TOPK; s++) {
            int best = 0; float bv = -3.4e38f;
            #pragma unroll
            for (int i = 0; i < N_EXP; i++)
                if (lg[i] > bv) { bv = lg[i]; best = i; }
            sel[s] = best; sv[s] = bv; lg[best] = -3.4e38f;
        }
        float mx = sv[0];
        float ex[TOPK], sum = 0.f;
        #pragma unroll
        for (int s = 0; s < TOPK; s++) { ex[s] = __expf(sv[s] - mx); sum += ex[s]; }
        float inv = 1.f / sum;
        #pragma unroll
        for (int s = 0; s < TOPK; s++) {
            int e = sel[s];
            int pos = atomicAdd(&g_cnt[e], 1);
            g_list[e * T_TOK + pos] = t * TOPK + s;
            g_rw[t * TOPK + s] = ex[s] * inv;
        }
    }
}

// ============================================================================
// phase A: h = silu(x@Wg^T)*(x@Wu^T)*rw     fp16 MMA m16n8k16, fp32 accum
// BM=128, BN=64, BK=32; 8 warps 2M x 4N; warp tile 64x16 per tensor.
// Merged-B ldsm4; manual kt unroll x2. (round-14 best)
// ============================================================================
__global__ __launch_bounds__(256, 2) void phaseA_kernel(
    const float* __restrict__ wg, const float* __restrict__ wu)
{
    const int e    = blockIdx.z;
    const int cnt  = g_cnt[e];
    const int row0 = blockIdx.x * 128;
    if (row0 >= cnt) return;
    const int col0 = blockIdx.y * 64;

    extern __shared__ __align__(16) char dsm[];
    __shared__ int toks[128];

    const uint32_t S   = sptr(dsm);
    const uint32_t A0  = S;
    const uint32_t G0  = S + 10240;
    const uint32_t U0  = S + 15360;
    const uint32_t STG = 20480;

    const int tid = threadIdx.x;
    if (tid < 128) {
        int r = row0 + tid;
        toks[tid] = (r < cnt) ? g_list[e * T_TOK + r] : -1;
    }
    __syncthreads();

    const float* wgE = wg + (size_t)e * I_DIM * H_DIM + (size_t)col0 * H_DIM;
    const float* wuE = wu + (size_t)e * I_DIM * H_DIM + (size_t)col0 * H_DIM;

    const int warp = tid >> 5, lane = tid & 31;
    const int gid  = lane >> 2, tcol = lane & 3;
    const int mw0  = (warp & 1) * 64;
    const int nw0  = (warp >> 1) * 16;

    const uint32_t aoff = (uint32_t)(mw0 + (lane & 15)) * PITCH + ((lane >> 4) * 16);
    const uint32_t boff = (uint32_t)(nw0 + ((lane >> 4) << 3) + (lane & 7)) * PITCH
                        + (((lane >> 3) & 1) * 16);

    float accG[4][2][4] = {};
    float accU[4][2][4] = {};
    float4 gq[2], uq[2];

    const int wr = tid >> 2;
    const int wc = tid & 3;

    auto ldgA = [&](int kt, int buf) {
        const int k0 = kt * 32;
        #pragma unroll
        for (int j = 0; j < 2; j++) {
            int idx = j * 256 + tid;
            int r   = idx >> 2;
            int ch  = idx & 3;
            int pkk = toks[r];
            const __half* src = (pkk >= 0)
                ? &g_xh[(size_t)(pkk >> 3) * H_DIM + k0 + ch * 8] : g_xh;
            cp16(A0 + buf * STG + r * PITCH + ch * 16, src, pkk >= 0);
        }
    };
    auto ldgW = [&](int kt) {
        const int k0 = kt * 32;
        const float* sg = &wgE[(size_t)wr * H_DIM + k0 + wc * 8];
        const float* su = &wuE[(size_t)wr * H_DIM + k0 + wc * 8];
        gq[0] = *(const float4*)sg; gq[1] = *(const float4*)(sg + 4);
        uq[0] = *(const float4*)su; uq[1] = *(const float4*)(su + 4);
    };
    auto stsW = [&](int buf) {
        uint32_t a = G0 + buf * STG + wr * PITCH + wc * 16;
        sts128(a, pk2(gq[0].x, gq[0].y), pk2(gq[0].z, gq[0].w),
                  pk2(gq[1].x, gq[1].y), pk2(gq[1].z, gq[1].w));
        uint32_t b = U0 + buf * STG + wr * PITCH + wc * 16;
        sts128(b, pk2(uq[0].x, uq[0].y), pk2(uq[0].z, uq[0].w),
                  pk2(uq[1].x, uq[1].y), pk2(uq[1].z, uq[1].w));
    };
    auto compute = [&](int buf) {
        const uint32_t Ab = A0 + buf * STG + aoff;
        const uint32_t Gb = G0 + buf * STG + boff;
        const uint32_t Ub = U0 + buf * STG + boff;
        #pragma unroll
        for (int kc = 0; kc < 2; kc++) {
            const uint32_t kb = kc * 32;
            uint32_t a[4][4];
            #pragma unroll
            for (int mf = 0; mf < 4; mf++) ldsm4(a[mf], Ab + mf * 16 * PITCH + kb);
            uint32_t bg[4], bu[4];
            ldsm4(bg, Gb + kb);
            ldsm4(bu, Ub + kb);
            #pragma unroll
            for (int mf = 0; mf < 4; mf++) {
                mma16(accG[mf][0], a[mf], bg[0], bg[1]);
                mma16(accG[mf][1], a[mf], bg[2], bg[3]);
                mma16(accU[mf][0], a[mf], bu[0], bu[1]);
                mma16(accU[mf][1], a[mf], bu[2], bu[3]);
            }
        }
    };

    const int KT = H_DIM / 32;   // 64 (even)
    ldgA(0, 0); CP_COMMIT();
    ldgW(0);

    for (int kt = 0; kt < KT; kt += 2) {
        stsW(0);
        CP_WAIT0();
        __syncthreads();
        ldgA(kt + 1, 1); CP_COMMIT();
        ldgW(kt + 1);
        compute(0);
        stsW(1);
        CP_WAIT0();
        __syncthreads();
        if (kt + 2 < KT) {
            ldgA(kt + 2, 0); CP_COMMIT();
            ldgW(kt + 2);
        }
        compute(1);
    }

    // epilogue: silu(g)*u*rw -> g_h (fp16)
    #pragma unroll
    for (int mf = 0; mf < 4; mf++) {
        #pragma unroll
        for (int half = 0; half < 2; half++) {
            int rl = mw0 + mf * 16 + gid + half * 8;
            int pkk = toks[rl];
            if (pkk < 0) continue;
            float w = g_rw[pkk];
            #pragma unroll
            for (int nf = 0; nf < 2; nf++) {
                int c = col0 + nw0 + nf * 8 + 2 * tcol;
                float g0 = accG[mf][nf][half * 2 + 0];
                float g1 = accG[mf][nf][half * 2 + 1];
                float u0 = accU[mf][nf][half * 2 + 0];
                float u1 = accU[mf][nf][half * 2 + 1];
                float h0 = (g0 / (1.f + __expf(-g0))) * u0 * w;
                float h1 = (g1 / (1.f + __expf(-g1))) * u1 * w;
                *(uint32_t*)&g_h[(size_t)pkk * I_DIM + c] = pk2(h0, h1);
            }
        }
    }
}

// ============================================================================
// phase B: out[token] += h[pk] @ Wd^T   fp16 MMA, fp32 accum, atomic epilogue
// BM=128, BN=128, BK=32; 8 warps 2M x 4N; warp tile 64x32. Unroll x2.
// ============================================================================
__global__ __launch_bounds__(256, 2) void phaseB_kernel(
    const float* __restrict__ wd, float* __restrict__ out)
{
    const int e    = blockIdx.z;
    const int cnt  = g_cnt[e];
    const int row0 = blockIdx.x * 128;
    if (row0 >= cnt) return;
    const int col0 = blockIdx.y * 128;

    extern __shared__ __align__(16) char dsm[];
    __shared__ int toks[128];

    const uint32_t S   = sptr(dsm);
    const uint32_t H0  = S;
    const uint32_t D0  = S + 10240;
    const uint32_t STG = 20480;

    const int tid = threadIdx.x;
    if (tid < 128) {
        int r = row0 + tid;
        toks[tid] = (r < cnt) ? g_list[e * T_TOK + r] : -1;
    }
    __syncthreads();

    const float* wdE = wd + (size_t)e * H_DIM * I_DIM + (size_t)col0 * I_DIM;

    const int warp = tid >> 5, lane = tid & 31;
    const int gid  = lane >> 2, tcol = lane & 3;
    const int mw0  = (warp & 1) * 64;
    const int nw0  = (warp >> 1) * 32;

    const uint32_t aoff = (uint32_t)(mw0 + (lane & 15)) * PITCH + ((lane >> 4) * 16);
    const uint32_t boff = (uint32_t)(nw0 + (lane & 15)) * PITCH + ((lane >> 4) * 16);

    float acc[4][4][4] = {};
    float4 dq[4];

    auto ldgH = [&](int kt, int buf) {
        const int k0 = kt * 32;
        #pragma unroll
        for (int j = 0; j < 2; j++) {
            int idx = j * 256 + tid;
            int r   = idx >> 2;
            int ch  = idx & 3;
            int pkk = toks[r];
            const __half* src = (pkk >= 0)
                ? &g_h[(size_t)pkk * I_DIM + k0 + ch * 8] : g_h;
            cp16(H0 + buf * STG + r * PITCH + ch * 16, src, pkk >= 0);
        }
    };
    auto ldgW = [&](int kt) {
        const int k0 = kt * 32;
        #pragma unroll
        for (int j = 0; j < 2; j++) {
            int idx = j * 256 + tid;
            int r   = idx >> 2;
            int ch  = idx & 3;
            const float* s = &wdE[(size_t)r * I_DIM + k0 + ch * 8];
            dq[j * 2]     = *(const float4*)s;
            dq[j * 2 + 1] = *(const float4*)(s + 4);
        }
    };
    auto stsW = [&](int buf) {
        #pragma unroll
        for (int j = 0; j < 2; j++) {
            int idx = j * 256 + tid;
            int r   = idx >> 2;
            int ch  = idx & 3;
            uint32_t a = D0 + buf * STG + r * PITCH + ch * 16;
            sts128(a, pk2(dq[j*2].x, dq[j*2].y), pk2(dq[j*2].z, dq[j*2].w),
                      pk2(dq[j*2+1].x, dq[j*2+1].y), pk2(dq[j*2+1].z, dq[j*2+1].w));
        }
    };
    auto compute = [&](int buf) {
        const uint32_t Hb = H0 + buf * STG + aoff;
        const uint32_t Db = D0 + buf * STG + boff;
        #pragma unroll
        for (int kc = 0; kc < 2; kc++) {
            const uint32_t kb = kc * 32;
            uint32_t a[4][4];
            #pragma unroll
            for (int mf = 0; mf < 4; mf++) ldsm4(a[mf], Hb + mf * 16 * PITCH + kb);
            uint32_t b[2][4];
            #pragma unroll
            for (int g = 0; g < 2; g++) ldsm4(b[g], Db + g * 16 * PITCH + kb);
            #pragma unroll
            for (int mf = 0; mf < 4; mf++)
                #pragma unroll
                for (int g = 0; g < 2; g++) {
                    mma16(acc[mf][g * 2 + 0], a[mf], b[g][0], b[g][2]);
                    mma16(acc[mf][g * 2 + 1], a[mf], b[g][1], b[g][3]);
                }
        }
    };

    const int KT = I_DIM / 32;   // 24 (even)
    ldgH(0, 0); CP_COMMIT();
    ldgW(0);

    for (int kt = 0; kt < KT; kt += 2) {
        stsW(0);
        CP_WAIT0();
        __syncthreads();
        ldgH(kt + 1, 1); CP_COMMIT();
        ldgW(kt + 1);
        compute(0);
        stsW(1);
        CP_WAIT0();
        __syncthreads();
        if (kt + 2 < KT) {
            ldgH(kt + 2, 0); CP_COMMIT();
            ldgW(kt + 2);
        }
        compute(1);
    }

    // epilogue: atomic accumulate into out
    #pragma unroll
    for (int mf = 0; mf < 4; mf++) {
        #pragma unroll
        for (int half = 0; half < 2; half++) {
            int rl = mw0 + mf * 16 + gid + half * 8;
            int pkk = toks[rl];
            if (pkk < 0) continue;
            float* orow = out + (size_t)(pkk >> 3) * H_DIM;
            #pragma unroll
            for (int nf = 0; nf < 4; nf++) {
                int c = col0 + nw0 + nf * 8 + 2 * tcol;
                atomicAdd(&orow[c],     acc[mf][nf][half * 2 + 0]);
                atomicAdd(&orow[c + 1], acc[mf][nf][half * 2 + 1]);
            }
        }
    }
}

// ---------------------------------------------------------------------------
extern "C" void kernel_launch(void* const* d_in, const int* in_sizes, int n_in,
                              void* d_out, int out_size)
{
    const float* x  = (const float*)d_in[0];
    const float* gw = (const float*)d_in[1];
    const float* wg = (const float*)d_in[2];
    const float* wu = (const float*)d_in[3];
    const float* wd = (const float*)d_in[4];
    float* out = (float*)d_out;

    const int smemAB = 2 * 20480;   // 40960 B
    static bool attr_done = false;
    if (!attr_done) {
        cudaFuncSetAttribute(phaseA_kernel, cudaFuncAttributeMaxDynamicSharedMemorySize, smemAB);
        cudaFuncSetAttribute(phaseB_kernel, cudaFuncAttributeMaxDynamicSharedMemorySize, smemAB);
        attr_done = true;
    }

    init_kernel<<<1, 32>>>();
    router_kernel<<<T_TOK, 256>>>(x, gw, out);
    phaseA_kernel<<<dim3(16, I_DIM / 64, N_EXP), 256, smemAB>>>(wg, wu);
    phaseB_kernel<<<dim3(16, H_DIM / 128, N_EXP), 256, smemAB>>>(wd, out);
}

// round 17
// speedup vs baseline: 1.0761x; 1.0588x over previous
#include <cuda_runtime.h>
#include <cuda_fp16.h>
#include <cstdint>
#include <cstddef>

#define T_TOK 2048
#define H_DIM 2048
#define N_EXP 32
#define I_DIM 768
#define TOPK  8
#define PITCH 80        // smem row pitch bytes (32 halves + 16B skew)

// -------- static device scratch --------------------------------------------
__device__ int   g_cnt[N_EXP];
__device__ int   g_list[N_EXP * T_TOK];
__device__ float g_rw[T_TOK * TOPK];
__device__ __align__(16) __half g_xh[(size_t)T_TOK * H_DIM];        // 8 MB  x fp16
__device__ __align__(16) __half g_h[(size_t)T_TOK * TOPK * I_DIM];  // 25 MB h fp16

// -------- helpers -----------------------------------------------------------
__device__ __forceinline__ uint32_t sptr(const void* p) {
    return (uint32_t)__cvta_generic_to_shared(p);
}
__device__ __forceinline__ uint32_t pk2(float a, float b) {
    __half2 h = __floats2half2_rn(a, b);
    return *(uint32_t*)&h;
}
__device__ __forceinline__ void sts128(uint32_t a, uint32_t x0, uint32_t x1,
                                       uint32_t x2, uint32_t x3) {
    asm volatile("st.shared.v4.b32 [%0], {%1,%2,%3,%4};"
                 :: "r"(a), "r"(x0), "r"(x1), "r"(x2), "r"(x3));
}
__device__ __forceinline__ void cp16(uint32_t dst, const void* src, int valid) {
    asm volatile("cp.async.cg.shared.global [%0], [%1], 16, %2;"
                 :: "r"(dst), "l"(src), "r"(valid ? 16 : 0));
}
#define CP_COMMIT() asm volatile("cp.async.commit_group;")
#define CP_WAIT1()  asm volatile("cp.async.wait_group 1;")
#define CP_WAIT0()  asm volatile("cp.async.wait_group 0;")

__device__ __forceinline__ void ldsm4(uint32_t* r, uint32_t a) {
    asm volatile("ldmatrix.sync.aligned.m8n8.x4.shared.b16 {%0,%1,%2,%3}, [%4];"
                 : "=r"(r[0]), "=r"(r[1]), "=r"(r[2]), "=r"(r[3]) : "r"(a));
}
__device__ __forceinline__ void mma16(float* d, const uint32_t* a,
                                      uint32_t b0, uint32_t b1) {
    asm volatile(
        "mma.sync.aligned.m16n8k16.row.col.f32.f16.f16.f32 "
        "{%0,%1,%2,%3},{%4,%5,%6,%7},{%8,%9},{%0,%1,%2,%3};"
        : "+f"(d[0]), "+f"(d[1]), "+f"(d[2]), "+f"(d[3])
        : "r"(a[0]), "r"(a[1]), "r"(a[2]), "r"(a[3]), "r"(b0), "r"(b1));
}

// -------- init: zero expert counters only -------------------------------------
__global__ void init_kernel()
{
    if (threadIdx.x < N_EXP) g_cnt[threadIdx.x] = 0;
}

// -------- router (emits x fp16 to g_xh; zeroes its token's out row) -----------
__global__ __launch_bounds__(256) void router_kernel(
    const float* __restrict__ x, const float* __restrict__ gw,
    float* __restrict__ out)
{
    __shared__ float xs[H_DIM];
    __shared__ float logits[N_EXP];

    const int t = blockIdx.x;
    const float* xr = x + (size_t)t * H_DIM;
    for (int i = threadIdx.x; i < H_DIM; i += 256) xs[i] = xr[i];

    {
        float4 z = make_float4(0.f, 0.f, 0.f, 0.f);
        float4* orow = (float4*)(out + (size_t)t * H_DIM);
        orow[threadIdx.x]       = z;
        orow[threadIdx.x + 256] = z;
    }
    __syncthreads();

    {
        const int b = threadIdx.x * 8;
        uint4 o;
        o.x = pk2(xs[b + 0], xs[b + 1]);
        o.y = pk2(xs[b + 2], xs[b + 3]);
        o.z = pk2(xs[b + 4], xs[b + 5]);
        o.w = pk2(xs[b + 6], xs[b + 7]);
        *(uint4*)&g_xh[(size_t)t * H_DIM + b] = o;
    }

    const int warp = threadIdx.x >> 5;
    const int lane = threadIdx.x & 31;

    float acc[4] = {0.f, 0.f, 0.f, 0.f};
    for (int k = lane; k < H_DIM; k += 32) {
        float xv = xs[k];
        #pragma unroll
        for (int q = 0; q < 4; q++)
            acc[q] = fmaf(xv, gw[(size_t)(warp * 4 + q) * H_DIM + k], acc[q]);
    }
    #pragma unroll
    for (int q = 0; q < 4; q++) {
        float v = acc[q];
        #pragma unroll
        for (int off = 16; off; off >>= 1)
            v += __shfl_down_sync(0xffffffffu, v, off);
        if (lane == 0) logits[warp * 4 + q] = v;
    }
    __syncthreads();

    if (threadIdx.x == 0) {
        float lg[N_EXP];
        #pragma unroll
        for (int i = 0; i < N_EXP; i++) lg[i] = logits[i];
        int   sel[TOPK];
        float sv[TOPK];
        #pragma unroll
        for (int s = 0; s < TOPK; s++) {
            int best = 0; float bv = -3.4e38f;
            #pragma unroll
            for (int i = 0; i < N_EXP; i++)
                if (lg[i] > bv) { bv = lg[i]; best = i; }
            sel[s] = best; sv[s] = bv; lg[best] = -3.4e38f;
        }
        float mx = sv[0];
        float ex[TOPK], sum = 0.f;
        #pragma unroll
        for (int s = 0; s < TOPK; s++) { ex[s] = __expf(sv[s] - mx); sum += ex[s]; }
        float inv = 1.f / sum;
        #pragma unroll
        for (int s = 0; s < TOPK; s++) {
            int e = sel[s];
            int pos = atomicAdd(&g_cnt[e], 1);
            g_list[e * T_TOK + pos] = t * TOPK + s;
            g_rw[t * TOPK + s] = ex[s] * inv;
        }
    }
}

// ============================================================================
// phase A: h = silu(x@Wg^T)*(x@Wu^T)*rw     fp16 MMA m16n8k16, fp32 accum
// BM=128, BN=64, BK=32; 8 warps 2M x 4N; warp tile 64x16 per tensor.
// 3 A-buffers + wait_group(1): next-kt loads issued BEFORE the wait/sync.
// smem/CTA = 3*10240 (A) + 2*5120 (G) + 2*5120 (U) = 51200 B
// ============================================================================
__global__ __launch_bounds__(256, 2) void phaseA_kernel(
    const float* __restrict__ wg, const float* __restrict__ wu)
{
    const int e    = blockIdx.z;
    const int cnt  = g_cnt[e];
    const int row0 = blockIdx.x * 128;
    if (row0 >= cnt) return;
    const int col0 = blockIdx.y * 64;

    extern __shared__ __align__(16) char dsm[];
    __shared__ int toks[128];

    const uint32_t S   = sptr(dsm);
    const uint32_t A0  = S;            // 3 bufs, stride 10240
    const uint32_t G0  = S + 30720;    // 2 bufs, stride 5120
    const uint32_t U0  = S + 40960;    // 2 bufs, stride 5120

    const int tid = threadIdx.x;
    if (tid < 128) {
        int r = row0 + tid;
        toks[tid] = (r < cnt) ? g_list[e * T_TOK + r] : -1;
    }
    __syncthreads();

    const float* wgE = wg + (size_t)e * I_DIM * H_DIM + (size_t)col0 * H_DIM;
    const float* wuE = wu + (size_t)e * I_DIM * H_DIM + (size_t)col0 * H_DIM;

    const int warp = tid >> 5, lane = tid & 31;
    const int gid  = lane >> 2, tcol = lane & 3;
    const int mw0  = (warp & 1) * 64;
    const int nw0  = (warp >> 1) * 16;

    const uint32_t aoff = (uint32_t)(mw0 + (lane & 15)) * PITCH + ((lane >> 4) * 16);
    // merged-B ldsm4 mapping (r14)
    const uint32_t boff = (uint32_t)(nw0 + ((lane >> 4) << 3) + (lane & 7)) * PITCH
                        + (((lane >> 3) & 1) * 16);

    float accG[4][2][4] = {};
    float accU[4][2][4] = {};
    float4 gq[2], uq[2];

    const int wr = tid >> 2;        // weight row 0..63
    const int wc = tid & 3;         // 16B chunk 0..3

    auto ldgA = [&](int kt, int ab) {
        const int k0 = kt * 32;
        #pragma unroll
        for (int j = 0; j < 2; j++) {
            int idx = j * 256 + tid;
            int r   = idx >> 2;
            int ch  = idx & 3;
            int pkk = toks[r];
            const __half* src = (pkk >= 0)
                ? &g_xh[(size_t)(pkk >> 3) * H_DIM + k0 + ch * 8] : g_xh;
            cp16(A0 + ab * 10240 + r * PITCH + ch * 16, src, pkk >= 0);
        }
    };
    auto ldgW = [&](int kt) {
        const int k0 = kt * 32;
        const float* sg = &wgE[(size_t)wr * H_DIM + k0 + wc * 8];
        const float* su = &wuE[(size_t)wr * H_DIM + k0 + wc * 8];
        gq[0] = *(const float4*)sg; gq[1] = *(const float4*)(sg + 4);
        uq[0] = *(const float4*)su; uq[1] = *(const float4*)(su + 4);
    };
    auto stsW = [&](int wb) {
        uint32_t a = G0 + wb * 5120 + wr * PITCH + wc * 16;
        sts128(a, pk2(gq[0].x, gq[0].y), pk2(gq[0].z, gq[0].w),
                  pk2(gq[1].x, gq[1].y), pk2(gq[1].z, gq[1].w));
        uint32_t b = U0 + wb * 5120 + wr * PITCH + wc * 16;
        sts128(b, pk2(uq[0].x, uq[0].y), pk2(uq[0].z, uq[0].w),
                  pk2(uq[1].x, uq[1].y), pk2(uq[1].z, uq[1].w));
    };
    auto compute = [&](int ab, int wb) {
        const uint32_t Ab = A0 + ab * 10240 + aoff;
        const uint32_t Gb = G0 + wb * 5120 + boff;
        const uint32_t Ub = U0 + wb * 5120 + boff;
        #pragma unroll
        for (int kc = 0; kc < 2; kc++) {
            const uint32_t kb = kc * 32;
            uint32_t a[4][4];
            #pragma unroll
            for (int mf = 0; mf < 4; mf++) ldsm4(a[mf], Ab + mf * 16 * PITCH + kb);
            uint32_t bg[4], bu[4];
            ldsm4(bg, Gb + kb);
            ldsm4(bu, Ub + kb);
            #pragma unroll
            for (int mf = 0; mf < 4; mf++) {
                mma16(accG[mf][0], a[mf], bg[0], bg[1]);
                mma16(accG[mf][1], a[mf], bg[2], bg[3]);
                mma16(accU[mf][0], a[mf], bu[0], bu[1]);
                mma16(accU[mf][1], a[mf], bu[2], bu[3]);
            }
        }
    };

    const int KT = H_DIM / 32;   // 64
    ldgA(0, 0); CP_COMMIT();
    ldgW(0);

    int ab = 0, abn = 1;
    for (int kt = 0; kt < KT; kt++) {
        stsW(kt & 1);
        if (kt + 1 < KT) {
            ldgA(kt + 1, abn); CP_COMMIT();
            ldgW(kt + 1);
            CP_WAIT1();
        } else {
            CP_WAIT0();
        }
        __syncthreads();
        compute(ab, kt & 1);
        ab = abn;
        abn = (abn == 2) ? 0 : abn + 1;
    }

    // epilogue: silu(g)*u*rw -> g_h (fp16)
    #pragma unroll
    for (int mf = 0; mf < 4; mf++) {
        #pragma unroll
        for (int half = 0; half < 2; half++) {
            int rl = mw0 + mf * 16 + gid + half * 8;
            int pkk = toks[rl];
            if (pkk < 0) continue;
            float w = g_rw[pkk];
            #pragma unroll
            for (int nf = 0; nf < 2; nf++) {
                int c = col0 + nw0 + nf * 8 + 2 * tcol;
                float g0 = accG[mf][nf][half * 2 + 0];
                float g1 = accG[mf][nf][half * 2 + 1];
                float u0 = accU[mf][nf][half * 2 + 0];
                float u1 = accU[mf][nf][half * 2 + 1];
                float h0 = (g0 / (1.f + __expf(-g0))) * u0 * w;
                float h1 = (g1 / (1.f + __expf(-g1))) * u1 * w;
                *(uint32_t*)&g_h[(size_t)pkk * I_DIM + c] = pk2(h0, h1);
            }
        }
    }
}

// ============================================================================
// phase B: out[token] += h[pk] @ Wd^T   fp16 MMA, fp32 accum, atomic epilogue
// BM=128, BN=128, BK=32; 8 warps 2M x 4N; warp tile 64x32.
// 3 H-buffers + wait_group(1); loads issued before wait/sync.
// smem/CTA = 3*10240 (H) + 2*10240 (D) = 51200 B
// ============================================================================
__global__ __launch_bounds__(256, 2) void phaseB_kernel(
    const float* __restrict__ wd, float* __restrict__ out)
{
    const int e    = blockIdx.z;
    const int cnt  = g_cnt[e];
    const int row0 = blockIdx.x * 128;
    if (row0 >= cnt) return;
    const int col0 = blockIdx.y * 128;

    extern __shared__ __align__(16) char dsm[];
    __shared__ int toks[128];

    const uint32_t S   = sptr(dsm);
    const uint32_t H0  = S;            // 3 bufs, stride 10240
    const uint32_t D0  = S + 30720;    // 2 bufs, stride 10240

    const int tid = threadIdx.x;
    if (tid < 128) {
        int r = row0 + tid;
        toks[tid] = (r < cnt) ? g_list[e * T_TOK + r] : -1;
    }
    __syncthreads();

    const float* wdE = wd + (size_t)e * H_DIM * I_DIM + (size_t)col0 * I_DIM;

    const int warp = tid >> 5, lane = tid & 31;
    const int gid  = lane >> 2, tcol = lane & 3;
    const int mw0  = (warp & 1) * 64;
    const int nw0  = (warp >> 1) * 32;

    const uint32_t aoff = (uint32_t)(mw0 + (lane & 15)) * PITCH + ((lane >> 4) * 16);
    const uint32_t boff = (uint32_t)(nw0 + (lane & 15)) * PITCH + ((lane >> 4) * 16);

    float acc[4][4][4] = {};
    float4 dq[4];

    auto ldgH = [&](int kt, int hb) {
        const int k0 = kt * 32;
        #pragma unroll
        for (int j = 0; j < 2; j++) {
            int idx = j * 256 + tid;
            int r   = idx >> 2;
            int ch  = idx & 3;
            int pkk = toks[r];
            const __half* src = (pkk >= 0)
                ? &g_h[(size_t)pkk * I_DIM + k0 + ch * 8] : g_h;
            cp16(H0 + hb * 10240 + r * PITCH + ch * 16, src, pkk >= 0);
        }
    };
    auto ldgW = [&](int kt) {
        const int k0 = kt * 32;
        #pragma unroll
        for (int j = 0; j < 2; j++) {
            int idx = j * 256 + tid;
            int r   = idx >> 2;
            int ch  = idx & 3;
            const float* s = &wdE[(size_t)r * I_DIM + k0 + ch * 8];
            dq[j * 2]     = *(const float4*)s;
            dq[j * 2 + 1] = *(const float4*)(s + 4);
        }
    };
    auto stsW = [&](int wb) {
        #pragma unroll
        for (int j = 0; j < 2; j++) {
            int idx = j * 256 + tid;
            int r   = idx >> 2;
            int ch  = idx & 3;
            uint32_t a = D0 + wb * 10240 + r * PITCH + ch * 16;
            sts128(a, pk2(dq[j*2].x, dq[j*2].y), pk2(dq[j*2].z, dq[j*2].w),
                      pk2(dq[j*2+1].x, dq[j*2+1].y), pk2(dq[j*2+1].z, dq[j*2+1].w));
        }
    };
    auto compute = [&](int hb, int wb) {
        const uint32_t Hb = H0 + hb * 10240 + aoff;
        const uint32_t Db = D0 + wb * 10240 + boff;
        #pragma unroll
        for (int kc = 0; kc < 2; kc++) {
            const uint32_t kb = kc * 32;
            uint32_t a[4][4];
            #pragma unroll
            for (int mf = 0; mf < 4; mf++) ldsm4(a[mf], Hb + mf * 16 * PITCH + kb);
            uint32_t b[2][4];
            #pragma unroll
            for (int g = 0; g < 2; g++) ldsm4(b[g], Db + g * 16 * PITCH + kb);
            #pragma unroll
            for (int mf = 0; mf < 4; mf++)
                #pragma unroll
                for (int g = 0; g < 2; g++) {
                    mma16(acc[mf][g * 2 + 0], a[mf], b[g][0], b[g][2]);
                    mma16(acc[mf][g * 2 + 1], a[mf], b[g][1], b[g][3]);
                }
        }
    };

    const int KT = I_DIM / 32;   // 24
    ldgH(0, 0); CP_COMMIT();
    ldgW(0);

    int hb = 0, hbn = 1;
    for (int kt = 0; kt < KT; kt++) {
        stsW(kt & 1);
        if (kt + 1 < KT) {
            ldgH(kt + 1, hbn); CP_COMMIT();
            ldgW(kt + 1);
            CP_WAIT1();
        } else {
            CP_WAIT0();
        }
        __syncthreads();
        compute(hb, kt & 1);
        hb = hbn;
        hbn = (hbn == 2) ? 0 : hbn + 1;
    }

    // epilogue: atomic accumulate into out
    #pragma unroll
    for (int mf = 0; mf < 4; mf++) {
        #pragma unroll
        for (int half = 0; half < 2; half++) {
            int rl = mw0 + mf * 16 + gid + half * 8;
            int pkk = toks[rl];
            if (pkk < 0) continue;
            float* orow = out + (size_t)(pkk >> 3) * H_DIM;
            #pragma unroll
            for (int nf = 0; nf < 4; nf++) {
                int c = col0 + nw0 + nf * 8 + 2 * tcol;
                atomicAdd(&orow[c],     acc[mf][nf][half * 2 + 0]);
                atomicAdd(&orow[c + 1], acc[mf][nf][half * 2 + 1]);
            }
        }
    }
}

// ---------------------------------------------------------------------------
extern "C" void kernel_launch(void* const* d_in, const int* in_sizes, int n_in,
                              void* d_out, int out_size)
{
    const float* x  = (const float*)d_in[0];
    const float* gw = (const float*)d_in[1];
    const float* wg = (const float*)d_in[2];
    const float* wu = (const float*)d_in[3];
    const float* wd = (const float*)d_in[4];
    float* out = (float*)d_out;

    const int smemAB = 51200;   // per-CTA dynamic smem
    static bool attr_done = false;
    if (!attr_done) {
        cudaFuncSetAttribute(phaseA_kernel, cudaFuncAttributeMaxDynamicSharedMemorySize, smemAB);
        cudaFuncSetAttribute(phaseB_kernel, cudaFuncAttributeMaxDynamicSharedMemorySize, smemAB);
        attr_done = true;
    }

    init_kernel<<<1, 32>>>();
    router_kernel<<<T_TOK, 256>>>(x, gw, out);
    phaseA_kernel<<<dim3(16, I_DIM / 64, N_EXP), 256, smemAB>>>(wg, wu);
    phaseB_kernel<<<dim3(16, H_DIM / 128, N_EXP), 256, smemAB>>>(wd, out);
}